// round 2
// baseline (speedup 1.0000x reference)
#include <cuda_runtime.h>
#include <cstdint>

#define B 4
#define N 1024
#define F 256
#define W 32            // 32 x u32 words per 1024-bit row
#define FULL 0xFFFFFFFFu

// ---------------- scratch (device globals; no allocations allowed) ----------
__device__ unsigned g_bitsA[B][N][W];   // adj rows as bitmasks
__device__ unsigned g_bits1[B][N][W];   // (adj + I) rows as bitmasks
__device__ unsigned g_inc  [B][N][W];   // included = (adj2 != 0) rows as bitmasks
__device__ float    g_deg  [B][N];      // rowsum of adj1 (= popc(bits1 row))
__device__ int      g_perm [B][N];      // top_k permutation (stable)
__device__ int      g_K    [B];         // number of selected nodes

// Output layout (float32, concatenated):
//   x_p  : [B,N,F]  offset 0
//   pos_p: [B,N,3]  offset B*N*F
//   a    : [B,N,N]  offset B*N*F + B*N*3
//   mask : [B,N]    offset B*N*F + B*N*3 + B*N*N
#define OFF_X   0
#define OFF_P   (B*N*F)
#define OFF_A   (B*N*F + B*N*3)
#define OFF_M   (B*N*F + B*N*3 + B*N*N)

// ---------------- K0: pack adj rows into bitmasks + row degrees -------------
__global__ void pack_kernel(const float* __restrict__ adj) {
    int warp = (blockIdx.x * blockDim.x + threadIdx.x) >> 5;
    int lane = threadIdx.x & 31;
    if (warp >= B * N) return;
    int b = warp >> 10, i = warp & (N - 1);
    const float* row = adj + ((size_t)b * N + i) * N;
    unsigned my = 0;
    #pragma unroll
    for (int w = 0; w < W; ++w) {
        unsigned bal = __ballot_sync(FULL, row[w * 32 + lane] != 0.0f);
        if (w == lane) my = bal;
    }
    g_bitsA[b][i][lane] = my;
    unsigned m1 = my | ((lane == (i >> 5)) ? (1u << (i & 31)) : 0u);
    g_bits1[b][i][lane] = m1;
    int d = __popc(m1);
    #pragma unroll
    for (int o = 16; o; o >>= 1) d += __shfl_xor_sync(FULL, d, o);
    if (lane == 0) g_deg[b][i] = (float)d;
}

// ---------------- K1: included row i = OR of bitsA rows over k in bits1[i] --
__global__ void inc_kernel() {
    int warp = (blockIdx.x * blockDim.x + threadIdx.x) >> 5;
    int lane = threadIdx.x & 31;
    if (warp >= B * N) return;
    int b = warp >> 10, i = warp & (N - 1);
    unsigned myrow = g_bits1[b][i][lane];
    unsigned acc = 0;
    #pragma unroll 4
    for (int w = 0; w < W; ++w) {
        unsigned word = __shfl_sync(FULL, myrow, w);
        while (word) {
            int bit = __ffs(word) - 1;
            word &= word - 1;
            int k = w * 32 + bit;
            acc |= g_bitsA[b][k][lane];
        }
    }
    g_inc[b][i][lane] = acc;
}

// ---------------- K2: serial greedy selection (1 warp per batch) ------------
__device__ __forceinline__ int warp_argmin_masked(unsigned m, const float* sord, int lane) {
    // key = (order_bits << 32) | node ; order in [0,1) so bit pattern is monotone
    unsigned long long best = ~0ull;
    while (m) {
        int bit = __ffs(m) - 1;
        m &= m - 1;
        int node = lane * 32 + bit;
        unsigned long long k = ((unsigned long long)__float_as_uint(sord[node]) << 32) | (unsigned)node;
        if (k < best) best = k;
    }
    #pragma unroll
    for (int o = 16; o; o >>= 1) {
        unsigned long long other = __shfl_xor_sync(FULL, best, o);
        if (other < best) best = other;
    }
    return (int)(best & 0xFFFFFFFFu);
}

__global__ void select_kernel(const float* __restrict__ order, float* __restrict__ out_mask) {
    int b = blockIdx.x;
    int lane = threadIdx.x;
    __shared__ float sord[N];
    #pragma unroll
    for (int w = 0; w < W; ++w) sord[w * 32 + lane] = order[b * N + w * 32 + lane];
    __syncwarp();

    unsigned av = FULL;            // node_mask is all-true in this problem
    unsigned sel = 0;
    int idx = warp_argmin_masked(FULL, sord, lane);   // argmin over all nodes
    unsigned fr = ((idx >> 5) == lane) ? (1u << (idx & 31)) : 0u;

    int guard = 0;
    while (__any_sync(FULL, av) && guard++ < 4 * N) {
        bool fr_any = __any_sync(FULL, fr);           // frontier state BEFORE update
        unsigned cur = ((idx >> 5) == lane) ? (1u << (idx & 31)) : 0u;
        sel |= cur;
        unsigned exc = g_bits1[b][idx][lane];
        unsigned inc = g_inc [b][idx][lane];
        av &= ~cur & ~exc;
        fr = (fr | inc | (fr_any ? 0u : FULL)) & av;
        if (__any_sync(FULL, fr))
            idx = warp_argmin_masked(fr, sord, lane);
        // else: idx unchanged (matches reference)
    }

    // stable top_k permutation: selected nodes ascending, then unselected ascending
    int cnt = __popc(sel);
    int v = cnt;
    #pragma unroll
    for (int o = 1; o < 32; o <<= 1) {
        int n2 = __shfl_up_sync(FULL, v, o);
        if (lane >= o) v += n2;
    }
    int K = __shfl_sync(FULL, v, 31);
    int selpos = v - cnt;                 // exclusive prefix of selected
    int unspos = K + (lane * 32 - selpos);// K + exclusive prefix of unselected
    #pragma unroll
    for (int i = 0; i < 32; ++i) {
        int node = lane * 32 + i;
        if ((sel >> i) & 1u) g_perm[b][selpos++] = node;
        else                 g_perm[b][unspos++] = node;
    }
    if (lane == 0) g_K[b] = K;
    // mask output
    #pragma unroll
    for (int w = 0; w < W; ++w) {
        int j = w * 32 + lane;
        out_mask[b * N + j] = (j < K) ? 1.0f : 0.0f;
    }
}

// ---------------- K3: pooled features x_p and pos_p -------------------------
__global__ void xp_kernel(const float* __restrict__ x, const float* __restrict__ pos,
                          float* __restrict__ out_x, float* __restrict__ out_pos) {
    int b = blockIdx.y, k = blockIdx.x, f = threadIdx.x;   // 256 threads == F
    int K = g_K[b];
    size_t xo = ((size_t)b * N + k) * F + f;
    if (k >= K) {
        out_x[xo] = 0.0f;
        if (f < 3) out_pos[((size_t)b * N + k) * 3 + f] = 0.0f;
        return;
    }
    __shared__ unsigned sb[W];
    __shared__ int spk;
    if (f == 0) spk = g_perm[b][k];
    __syncthreads();
    int pk = spk;
    if (f < W) sb[f] = g_bits1[b][pk][f];
    __syncthreads();

    float acc = 0.0f;
    #pragma unroll 4
    for (int w = 0; w < W; ++w) {
        unsigned word = sb[w];
        while (word) {
            int bit = __ffs(word) - 1;
            word &= word - 1;
            int node = w * 32 + bit;
            acc += x[((size_t)b * N + node) * F + f];
        }
    }
    out_x[xo] = acc;

    if (f < 3) {
        float p = 0.0f;
        for (int w = 0; w < W; ++w) {
            unsigned word = sb[w];
            while (word) {
                int bit = __ffs(word) - 1;
                word &= word - 1;
                int node = w * 32 + bit;
                p += pos[((size_t)b * N + node) * 3 + f];
            }
        }
        out_pos[((size_t)b * N + k) * 3 + f] = p / g_deg[b][pk];
    }
}

// ---------------- K4: coarsened adjacency a[i][j] ---------------------------
__global__ void a_kernel(float* __restrict__ out_a) {
    int b = blockIdx.y, i = blockIdx.x, j = threadIdx.x;   // 1024 threads
    int K = g_K[b];
    size_t base = ((size_t)b * N + i) * N;
    if (i >= K) { out_a[base + j] = 0.0f; return; }
    __shared__ unsigned sb[W];
    __shared__ int spi;
    if (j == 0) spi = g_perm[b][i];
    __syncthreads();
    if (j < W) sb[j] = g_bits1[b][spi][j];
    __syncthreads();

    float v = 0.0f;
    if (j < K) {
        int pj = g_perm[b][j];
        int s = 0;
        #pragma unroll
        for (int w = 0; w < W; ++w) s += __popc(sb[w] & g_bitsA[b][pj][w]);
        v = (float)s;                 // adj2 entries are exact small integers
    }
    out_a[base + j] = v;
}

// ---------------- launch ----------------------------------------------------
extern "C" void kernel_launch(void* const* d_in, const int* in_sizes, int n_in,
                              void* d_out, int out_size) {
    const float *x = nullptr, *adj = nullptr, *pos = nullptr, *order = nullptr;
    for (int i = 0; i < n_in; ++i) {
        if      (in_sizes[i] == B * N * N) adj   = (const float*)d_in[i];
        else if (in_sizes[i] == B * N * F) x     = (const float*)d_in[i];
        else if (in_sizes[i] == B * N * 3) pos   = (const float*)d_in[i];
        else if (in_sizes[i] == B * N) { if (!order) order = (const float*)d_in[i]; }
        // second B*N-sized input is node_mask (all-true) — ignored
    }
    float* out = (float*)d_out;

    pack_kernel  <<<(B * N) / 8, 256>>>(adj);
    inc_kernel   <<<(B * N) / 8, 256>>>();
    select_kernel<<<B, 32>>>(order, out + OFF_M);
    {
        dim3 g(N, B);
        xp_kernel<<<g, F>>>(x, pos, out + OFF_X, out + OFF_P);
    }
    {
        dim3 g(N, B);
        a_kernel<<<g, N>>>(out + OFF_A);
    }
}

// round 4
// speedup vs baseline: 1.0108x; 1.0108x over previous
#include <cuda_runtime.h>
#include <cstdint>

#define B 4
#define N 1024
#define F 256
#define W 32            // 32 x u32 words per 1024-bit row
#define FULL 0xFFFFFFFFu

#define PACK_BLKS 512   // 512 blocks * 8 warps = 4096 rows
#define TOTAL_BLKS 2048 // extra 1536 blocks do the zero-fill
#define MAXK 344        // smem row-cache capacity in a_kernel (guarded fallback)
#define MAXL 128        // neighbor-list capacity in xp_kernel

// ---------------- scratch (device globals; no allocations allowed) ----------
__device__ unsigned g_bitsA [B][N][W];   // adj rows as bitmasks
__device__ unsigned g_bits1 [B][N][W];   // (adj + I) rows as bitmasks
__device__ uint2    g_excinc[B][N][W];   // {exc word, inc word} interleaved for select
__device__ int      g_perm  [B][N];      // top_k permutation (stable)
__device__ int      g_K     [B];         // number of selected nodes

// Output layout (float32, concatenated):
#define OFF_X   0
#define OFF_P   (B*N*F)
#define OFF_A   (B*N*F + B*N*3)
#define OFF_M   (B*N*F + B*N*3 + B*N*N)
#define NZERO4  ((B*N*F + B*N*3 + B*N*N) / 4)   // float4 count of x_p+pos_p+a region

// ---------------- K0: pack adj rows into bitmasks + zero-fill outputs -------
__global__ void pack_zero_kernel(const float* __restrict__ adj, float* __restrict__ out) {
    if (blockIdx.x >= PACK_BLKS) {
        // zero-fill x_p, pos_p, a regions with float4 stores
        int zb = blockIdx.x - PACK_BLKS;
        float4 z = make_float4(0.f, 0.f, 0.f, 0.f);
        float4* o = (float4*)out;
        for (int i = zb * blockDim.x + threadIdx.x; i < NZERO4;
             i += (TOTAL_BLKS - PACK_BLKS) * blockDim.x)
            o[i] = z;
        return;
    }
    int warp = (blockIdx.x * blockDim.x + threadIdx.x) >> 5;   // 0..4095
    int lane = threadIdx.x & 31;
    int b = warp >> 10, i = warp & (N - 1);
    // lane owns word `lane`: elements [lane*32, lane*32+32)
    const float4* r4 = (const float4*)(adj + ((size_t)b * N + i) * N) + lane * 8;
    unsigned w = 0;
    #pragma unroll
    for (int j = 0; j < 8; ++j) {
        float4 v = r4[j];
        w |= (v.x != 0.f ? 1u : 0u) << (4 * j)
           | (v.y != 0.f ? 1u : 0u) << (4 * j + 1)
           | (v.z != 0.f ? 1u : 0u) << (4 * j + 2)
           | (v.w != 0.f ? 1u : 0u) << (4 * j + 3);
    }
    g_bitsA[b][i][lane] = w;
    unsigned m1 = w | ((lane == (i >> 5)) ? (1u << (i & 31)) : 0u);
    g_bits1[b][i][lane] = m1;
}

// ---------------- K1: included row i = OR of bitsA rows over k in bits1[i] --
__global__ void inc_kernel() {
    int warp = (blockIdx.x * blockDim.x + threadIdx.x) >> 5;
    int lane = threadIdx.x & 31;
    int b = warp >> 10, i = warp & (N - 1);
    unsigned myrow = g_bits1[b][i][lane];
    unsigned acc = 0;
    #pragma unroll 4
    for (int w = 0; w < W; ++w) {
        unsigned word = __shfl_sync(FULL, myrow, w);
        while (word) {
            int bit = __ffs(word) - 1;
            word &= word - 1;
            acc |= g_bitsA[b][w * 32 + bit][lane];
        }
    }
    g_excinc[b][i][lane] = make_uint2(myrow, acc);
}

// ---------------- K2: serial greedy selection (1 warp per batch) ------------
__device__ __forceinline__ int warp_argmin_masked(unsigned m, const float* sord, int lane) {
    unsigned long long best = ~0ull;
    while (m) {
        int bit = __ffs(m) - 1;
        m &= m - 1;
        int node = lane * 32 + bit;
        unsigned long long k = ((unsigned long long)__float_as_uint(sord[node]) << 32) | (unsigned)node;
        if (k < best) best = k;
    }
    #pragma unroll
    for (int o = 16; o; o >>= 1) {
        unsigned long long other = __shfl_xor_sync(FULL, best, o);
        if (other < best) best = other;
    }
    return (int)(best & 0xFFFFFFFFu);
}

__global__ void select_kernel(const float* __restrict__ order, float* __restrict__ out_mask) {
    int b = blockIdx.x;
    int lane = threadIdx.x;
    __shared__ float sord[N];
    #pragma unroll
    for (int w = 0; w < W; ++w) sord[w * 32 + lane] = order[b * N + w * 32 + lane];
    __syncwarp();

    unsigned av = FULL;            // node_mask is all-true
    unsigned sel = 0;
    int idx = warp_argmin_masked(FULL, sord, lane);
    unsigned fr = ((idx >> 5) == lane) ? (1u << (idx & 31)) : 0u;

    int guard = 0;
    while (__any_sync(FULL, av) && guard++ < 4 * N) {
        bool fr_any = __any_sync(FULL, fr);
        unsigned cur = ((idx >> 5) == lane) ? (1u << (idx & 31)) : 0u;
        sel |= cur;
        uint2 eg = g_excinc[b][idx][lane];     // one LDG.64: {exc, inc}
        av &= ~cur & ~eg.x;
        fr = (fr | eg.y | (fr_any ? 0u : FULL)) & av;
        if (__any_sync(FULL, fr))
            idx = warp_argmin_masked(fr, sord, lane);
    }

    // stable top_k permutation: selected ascending, then unselected ascending
    int cnt = __popc(sel);
    int v = cnt;
    #pragma unroll
    for (int o = 1; o < 32; o <<= 1) {
        int n2 = __shfl_up_sync(FULL, v, o);
        if (lane >= o) v += n2;
    }
    int K = __shfl_sync(FULL, v, 31);
    int selpos = v - cnt;
    int unspos = K + (lane * 32 - selpos);
    #pragma unroll
    for (int i = 0; i < 32; ++i) {
        int node = lane * 32 + i;
        if ((sel >> i) & 1u) g_perm[b][selpos++] = node;
        else                 g_perm[b][unspos++] = node;
    }
    if (lane == 0) g_K[b] = K;
    #pragma unroll
    for (int w = 0; w < W; ++w) {
        int j = w * 32 + lane;
        out_mask[b * N + j] = (j < K) ? 1.0f : 0.0f;
    }
}

// ---------------- K3: pooled features x_p and pos_p (live rows only) --------
__global__ void xp_kernel(const float* __restrict__ x, const float* __restrict__ pos,
                          float* __restrict__ out_x, float* __restrict__ out_pos) {
    int b = blockIdx.y, k = blockIdx.x;
    if (k >= g_K[b]) return;                   // padding already zero-filled
    int f = threadIdx.x;                       // 256 threads == F
    __shared__ int spk, snn;
    __shared__ int list[MAXL];
    if (f == 0) spk = g_perm[b][k];
    __syncthreads();
    if (f < 32) {
        unsigned wd = g_bits1[b][spk][f];
        int c = __popc(wd);
        int v = c;
        #pragma unroll
        for (int o = 1; o < 32; o <<= 1) {
            int t = __shfl_up_sync(FULL, v, o);
            if (f >= o) v += t;
        }
        int p = v - c;                         // exclusive prefix
        while (wd) {
            int bt = __ffs(wd) - 1;
            wd &= wd - 1;
            list[p++] = f * 32 + bt;
        }
        if (f == 31) snn = v;
    }
    __syncthreads();
    int nn = snn;                              // == column degree (adj1 symmetric)

    float acc = 0.0f;
    #pragma unroll 4
    for (int i = 0; i < nn; ++i)
        acc += x[((size_t)b * N + list[i]) * F + f];
    out_x[((size_t)b * N + k) * F + f] = acc;

    if (f < 3) {
        float p = 0.0f;
        for (int i = 0; i < nn; ++i)
            p += pos[((size_t)b * N + list[i]) * 3 + f];
        out_pos[((size_t)b * N + k) * 3 + f] = p / (float)nn;
    }
}

// ---------------- K4: coarsened adjacency, one block per batch --------------
__global__ void a_kernel(float* __restrict__ out_a) {
    int b = blockIdx.x;
    int K = g_K[b];
    __shared__ unsigned srows[MAXK][33];       // pad 33: conflict-free across j
    __shared__ int sperm[MAXK];
    int KC = K < MAXK ? K : MAXK;
    for (int j = threadIdx.x; j < KC; j += blockDim.x) sperm[j] = g_perm[b][j];
    __syncthreads();
    for (int t = threadIdx.x; t < KC * W; t += blockDim.x) {
        int j = t >> 5, w = t & 31;
        srows[j][w] = g_bitsA[b][sperm[j]][w];
    }
    __syncthreads();
    for (int idx = threadIdx.x; idx < K * K; idx += blockDim.x) {
        int i = idx / K, j = idx - i * K;
        int pi = (i < KC) ? sperm[i] : g_perm[b][i];
        const unsigned* ri = (i < KC) ? &srows[i][0] : &g_bitsA[b][pi][0];
        const unsigned* rj;
        if (j < KC) rj = &srows[j][0];
        else        rj = &g_bitsA[b][g_perm[b][j]][0];
        int s = 0;
        #pragma unroll
        for (int w = 0; w < W; ++w) s += __popc(ri[w] & rj[w]);
        s += (rj[pi >> 5] >> (pi & 31)) & 1;   // diagonal self-term of (A+I)@A
        out_a[((size_t)b * N + i) * N + j] = (float)s;
    }
}

// ---------------- launch ----------------------------------------------------
extern "C" void kernel_launch(void* const* d_in, const int* in_sizes, int n_in,
                              void* d_out, int out_size) {
    const float *x = nullptr, *adj = nullptr, *pos = nullptr, *order = nullptr;
    for (int i = 0; i < n_in; ++i) {
        if      (in_sizes[i] == B * N * N) adj   = (const float*)d_in[i];
        else if (in_sizes[i] == B * N * F) x     = (const float*)d_in[i];
        else if (in_sizes[i] == B * N * 3) pos   = (const float*)d_in[i];
        else if (in_sizes[i] == B * N) { if (!order) order = (const float*)d_in[i]; }
    }
    float* out = (float*)d_out;

    pack_zero_kernel<<<TOTAL_BLKS, 256>>>(adj, out);
    inc_kernel      <<<(B * N) / 8, 256>>>();
    select_kernel   <<<B, 32>>>(order, out + OFF_M);
    {
        dim3 g(N, B);
        xp_kernel<<<g, F>>>(x, pos, out + OFF_X, out + OFF_P);
    }
    a_kernel<<<B, 1024>>>(out + OFF_A);
}